// round 3
// baseline (speedup 1.0000x reference)
#include <cuda_runtime.h>
#include <math.h>

// logZ of Conditional Poisson = log ESP_K(exp(w)), D=8192, K=256.
// Single persistent kernel: 32 co-resident blocks, software grid barriers.
//   Phase 1: per-warp 32-item DP in linear fp32 registers (shfl+FMA), then
//            in-block log-domain conv tree 32->64->128->256 (shared memory).
//   Phase 2: 4 global combine levels (32->16->8->4->2 polys), distinct
//            scratch regions per level (no aliasing -> L1-safe plain loads).
//   Phase 3: final merge computes ONLY coefficient K, writes out[0].

#define NC   257
#define NBLK 32
#define NWRP (NBLK * 8)        // 256 warps grid-wide

// Per-level regions (no address is ever read-then-rewritten in one launch):
#define OFF_LEAF 0             // 32 polys
#define OFF_L0   (32 * NC)     // 16 polys
#define OFF_L1   (48 * NC)     // 8 polys
#define OFF_L2   (56 * NC)     // 4 polys
#define OFF_L3   (60 * NC)     // 2 polys
__device__ float        g_buf[64 * NC];
__device__ unsigned int g_bar_count = 0;
__device__ unsigned int g_bar_gen   = 0;   // monotonic across graph replays

__device__ __forceinline__ void grid_barrier() {
    __syncthreads();
    __threadfence();                        // publish this block's writes
    if (threadIdx.x == 0) {
        const unsigned int gen = *((volatile unsigned int*)&g_bar_gen);
        if (atomicAdd(&g_bar_count, 1u) == NBLK - 1) {
            g_bar_count = 0;                // all arrived; none reading count
            __threadfence();
            *((volatile unsigned int*)&g_bar_gen) = gen + 1u;
        } else {
            while (*((volatile unsigned int*)&g_bar_gen) == gen) { }
        }
    }
    __syncthreads();
    __threadfence();                        // acquire other blocks' writes
}

// Warp computes two-pass logsumexp over terms a[i]+b[j-i], i in [0..j].
// Terms cached in registers; j <= 256 so <= 9 chunks of 32.
__device__ __forceinline__ float warp_conv(const float* __restrict__ a,
                                           const float* __restrict__ b,
                                           int j, int lane) {
    float tv[9];
    const int ntmax = (j >> 5) + 1;         // uniform across warp
    #pragma unroll
    for (int q = 0; q < 9; ++q) {
        if (q < ntmax) {
            const int i = lane + (q << 5);
            tv[q] = (i <= j) ? (a[i] + b[j - i]) : -1e30f;
        }
    }
    float m = -1e30f;
    #pragma unroll
    for (int q = 0; q < 9; ++q)
        if (q < ntmax) m = fmaxf(m, tv[q]);
    #pragma unroll
    for (int o = 16; o; o >>= 1) m = fmaxf(m, __shfl_xor_sync(0xffffffffu, m, o));
    float s = 0.0f;
    #pragma unroll
    for (int q = 0; q < 9; ++q)
        if (q < ntmax) s += __expf(tv[q] - m);
    #pragma unroll
    for (int o = 16; o; o >>= 1) s += __shfl_xor_sync(0xffffffffu, s, o);
    return m + __logf(s);                   // valid on lane 0 (full reduce: all)
}

__global__ __launch_bounds__(256) void cp_kernel(const float* __restrict__ w,
                                                 const int* __restrict__ Kp,
                                                 float* __restrict__ out) {
    __shared__ float sP[8 * 33];
    __shared__ float sQ[4 * 65];
    __shared__ float sR[2 * 129];

    const int tid  = threadIdx.x;
    const int lane = tid & 31;
    const int warp = tid >> 5;
    const int gw   = blockIdx.x * 8 + warp;

    // ---- Phase 1a: 32-item chunk DP, linear domain, registers only ----
    {
        float x = __expf(w[(blockIdx.x * 8 + warp) * 32 + lane]);
        float v = 0.0f;                     // lane l holds ESP_{l+1}
        #pragma unroll
        for (int it = 0; it < 32; ++it) {
            const float xi = __shfl_sync(0xffffffffu, x, it);
            float prev = __shfl_up_sync(0xffffffffu, v, 1);
            if (lane == 0) prev = 1.0f;
            v = fmaf(xi, prev, v);
        }
        if (lane == 0) sP[warp * 33] = 0.0f;
        sP[warp * 33 + lane + 1] = __logf(v);
    }
    __syncthreads();

    // ---- Phase 1b: in-block conv tree (shared memory, two-pass) ----
    for (int idx = tid; idx < 4 * 65; idx += 256) {
        const int c = idx / 65, j = idx % 65;
        const float* a = sP + (2 * c) * 33;
        const float* b = a + 33;
        const int lo = j > 32 ? j - 32 : 0, hi = j < 32 ? j : 32;
        float m = -1e30f;
        #pragma unroll 4
        for (int i = lo; i <= hi; ++i) m = fmaxf(m, a[i] + b[j - i]);
        float s = 0.0f;
        #pragma unroll 4
        for (int i = lo; i <= hi; ++i) s += __expf(a[i] + b[j - i] - m);
        sQ[c * 65 + j] = m + __logf(s);
    }
    __syncthreads();
    for (int idx = tid; idx < 2 * 129; idx += 256) {
        const int c = idx / 129, j = idx % 129;
        const float* a = sQ + (2 * c) * 65;
        const float* b = a + 65;
        const int lo = j > 64 ? j - 64 : 0, hi = j < 64 ? j : 64;
        float m = -1e30f;
        #pragma unroll 4
        for (int i = lo; i <= hi; ++i) m = fmaxf(m, a[i] + b[j - i]);
        float s = 0.0f;
        #pragma unroll 4
        for (int i = lo; i <= hi; ++i) s += __expf(a[i] + b[j - i] - m);
        sR[c * 129 + j] = m + __logf(s);
    }
    __syncthreads();
    for (int j = tid; j < NC; j += 256) {
        const float* a = sR;
        const float* b = sR + 129;
        const int lo = j > 128 ? j - 128 : 0, hi = j < 128 ? j : 128;
        float m = -1e30f;
        #pragma unroll 4
        for (int i = lo; i <= hi; ++i) m = fmaxf(m, a[i] + b[j - i]);
        float s = 0.0f;
        #pragma unroll 4
        for (int i = lo; i <= hi; ++i) s += __expf(a[i] + b[j - i] - m);
        g_buf[OFF_LEAF + blockIdx.x * NC + j] = m + __logf(s);
    }

    // ---- Phase 2: global combine levels, grid barriers in between ----
    const int srcoff[4] = {OFF_LEAF, OFF_L0, OFF_L1, OFF_L2};
    const int dstoff[4] = {OFF_L0,   OFF_L1, OFF_L2, OFF_L3};
    const int npairs[4] = {16, 8, 4, 2};

    #pragma unroll
    for (int lvl = 0; lvl < 4; ++lvl) {
        grid_barrier();
        const float* src = g_buf + srcoff[lvl];
        float*       dst = g_buf + dstoff[lvl];
        const int ntask = npairs[lvl] * NC;
        for (int t = gw; t < ntask; t += NWRP) {
            const int pair = t / NC;
            const int j    = t - pair * NC;
            const float* a = src + (2 * pair) * NC;
            const float  r = warp_conv(a, a + NC, j, lane);
            if (lane == 0) dst[pair * NC + j] = r;
        }
    }

    // ---- Phase 3: only coefficient K of the final merge ----
    grid_barrier();
    if (blockIdx.x == 0 && warp == 0) {
        int K = Kp ? *Kp : 256;
        K = min(max(K, 0), 256);
        const float* a = g_buf + OFF_L3;
        const float  r = warp_conv(a, a + NC, K, lane);
        if (lane == 0) out[0] = r;
    }
}

extern "C" void kernel_launch(void* const* d_in, const int* in_sizes, int n_in,
                              void* d_out, int out_size) {
    const float* w   = (const float*)d_in[0];
    const int*   Kp  = (n_in >= 2) ? (const int*)d_in[1] : nullptr;
    float*       out = (float*)d_out;
    (void)in_sizes; (void)out_size;
    cp_kernel<<<NBLK, 256>>>(w, Kp, out);
}

// round 4
// speedup vs baseline: 2.2621x; 2.2621x over previous
#include <cuda_runtime.h>
#include <math.h>

// logZ of Conditional Poisson = log ESP_K(exp(w)), D=8192, K=256.
// 4 graph nodes, PDL-overlapped:
//   K1: 16 blocks x 512 thr. Per-warp 32-item DP in linear fp32 registers,
//       then in-block log-domain conv tree 32->64->128->256->256 (512 items).
//   C8: 16 -> 8 polys  (warp per output coefficient, two-pass logsumexp conv)
//   C4: 8  -> 4 polys
//   F4: c[K] = LSE_i( (P0*P1)[i] + (P2*P3)[K-i] ): 257 warp tasks + a
//       last-block-done ticket reduction. No grid barrier anywhere.

#define NC   257
#define FULL 0xffffffffu

#define OFF0 0            // 16 polys (K1 out)
#define OFF1 (16 * NC)    // 8 polys  (C8 out)
#define OFF2 (24 * NC)    // 4 polys  (C4 out)
__device__ float        g_buf[28 * NC];
__device__ float        g_terms[NC];
__device__ unsigned int g_done = 0;

// Warp-cooperative two-pass logsumexp over a[i]+b[j-i], i in [0..j], j<=256.
__device__ __forceinline__ float warp_conv(const float* __restrict__ a,
                                           const float* __restrict__ b,
                                           int j, int lane) {
    float tv[9];
    const int ntmax = (j >> 5) + 1;          // uniform across warp
    #pragma unroll
    for (int q = 0; q < 9; ++q) {
        if (q < ntmax) {
            const int i = lane + (q << 5);
            tv[q] = (i <= j) ? (a[i] + b[j - i]) : -1e30f;
        }
    }
    float m = -1e30f;
    #pragma unroll
    for (int q = 0; q < 9; ++q)
        if (q < ntmax) m = fmaxf(m, tv[q]);
    #pragma unroll
    for (int o = 16; o; o >>= 1) m = fmaxf(m, __shfl_xor_sync(FULL, m, o));
    float s = 0.0f;
    #pragma unroll
    for (int q = 0; q < 9; ++q)
        if (q < ntmax) s += __expf(tv[q] - m);
    #pragma unroll
    for (int o = 16; o; o >>= 1) s += __shfl_xor_sync(FULL, s, o);
    return m + __logf(s);
}

// ---------------------------------------------------------------------------
// K1: 512 items per block -> one deg-256 truncated log-poly.
// ---------------------------------------------------------------------------
__global__ __launch_bounds__(512) void k1_kernel(const float* __restrict__ w) {
    __shared__ float sP[16 * 33];
    __shared__ float sQ[8 * 65];
    __shared__ float sR[4 * 129];
    __shared__ float sS[2 * 257];

    const int tid  = threadIdx.x;
    const int lane = tid & 31;
    const int warp = tid >> 5;                // 0..15

    // 32-item chunk DP (linear domain, registers only)
    {
        float x = __expf(w[(blockIdx.x * 16 + warp) * 32 + lane]);
        float v = 0.0f;                       // lane l holds ESP_{l+1}
        #pragma unroll
        for (int it = 0; it < 32; ++it) {
            const float xi = __shfl_sync(FULL, x, it);
            float prev = __shfl_up_sync(FULL, v, 1);
            if (lane == 0) prev = 1.0f;
            v = fmaf(xi, prev, v);
        }
        if (lane == 0) sP[warp * 33] = 0.0f;
        sP[warp * 33 + lane + 1] = __logf(v);
    }
    __syncthreads();

    // L1: 8 convs 32+32 -> 64
    for (int idx = tid; idx < 8 * 65; idx += 512) {
        const int c = idx / 65, j = idx % 65;
        const float* a = sP + (2 * c) * 33;
        const float* b = a + 33;
        const int lo = j > 32 ? j - 32 : 0, hi = j < 32 ? j : 32;
        float m = -1e30f;
        #pragma unroll 4
        for (int i = lo; i <= hi; ++i) m = fmaxf(m, a[i] + b[j - i]);
        float s = 0.0f;
        #pragma unroll 4
        for (int i = lo; i <= hi; ++i) s += __expf(a[i] + b[j - i] - m);
        sQ[c * 65 + j] = m + __logf(s);
    }
    __syncthreads();

    // L2: 4 convs 64+64 -> 128
    for (int idx = tid; idx < 4 * 129; idx += 512) {
        const int c = idx / 129, j = idx % 129;
        const float* a = sQ + (2 * c) * 65;
        const float* b = a + 65;
        const int lo = j > 64 ? j - 64 : 0, hi = j < 64 ? j : 64;
        float m = -1e30f;
        #pragma unroll 4
        for (int i = lo; i <= hi; ++i) m = fmaxf(m, a[i] + b[j - i]);
        float s = 0.0f;
        #pragma unroll 4
        for (int i = lo; i <= hi; ++i) s += __expf(a[i] + b[j - i] - m);
        sR[c * 129 + j] = m + __logf(s);
    }
    __syncthreads();

    // L3: 2 convs 128+128 -> 256 (full, no truncation loss)
    for (int idx = tid; idx < 2 * 257; idx += 512) {
        const int c = idx / 257, j = idx % 257;
        const float* a = sR + (2 * c) * 129;
        const float* b = a + 129;
        const int lo = j > 128 ? j - 128 : 0, hi = j < 128 ? j : 128;
        float m = -1e30f;
        #pragma unroll 4
        for (int i = lo; i <= hi; ++i) m = fmaxf(m, a[i] + b[j - i]);
        float s = 0.0f;
        #pragma unroll 4
        for (int i = lo; i <= hi; ++i) s += __expf(a[i] + b[j - i] - m);
        sS[c * 257 + j] = m + __logf(s);
    }
    __syncthreads();

    // L4: 1 conv 256+256 -> 256 (truncated), write to global
    for (int j = tid; j < NC; j += 512) {
        const float* a = sS;
        const float* b = sS + 257;
        float m = -1e30f;
        #pragma unroll 4
        for (int i = 0; i <= j; ++i) m = fmaxf(m, a[i] + b[j - i]);
        float s = 0.0f;
        #pragma unroll 4
        for (int i = 0; i <= j; ++i) s += __expf(a[i] + b[j - i] - m);
        g_buf[OFF0 + blockIdx.x * NC + j] = m + __logf(s);
    }
}

// ---------------------------------------------------------------------------
// Combine level: pairs of deg-256 polys, warp per output coefficient.
// ---------------------------------------------------------------------------
__global__ __launch_bounds__(256) void comb_kernel(int srcoff, int dstoff) {
    cudaGridDependencySynchronize();
    const int lane = threadIdx.x & 31;
    const int j    = blockIdx.x * 8 + (threadIdx.x >> 5);
    if (j >= NC) return;                      // uniform per warp
    const int pair = blockIdx.y;
    const float* a = g_buf + srcoff + (2 * pair) * NC;
    const float  r = warp_conv(a, a + NC, j, lane);
    if (lane == 0) g_buf[dstoff + pair * NC + j] = r;
}

// ---------------------------------------------------------------------------
// F4: final scalar from 4 polys. t_i = (P0*P1)[i] + (P2*P3)[K-i];
// answer = LSE_i t_i via last-block-done ticket reduction.
// ---------------------------------------------------------------------------
__global__ __launch_bounds__(256) void f4_kernel(const int* __restrict__ Kp,
                                                 float* __restrict__ out) {
    cudaGridDependencySynchronize();
    int K = Kp ? *Kp : 256;
    K = min(max(K, 0), 256);

    const int lane = threadIdx.x & 31;
    const int warp = threadIdx.x >> 5;
    const int gw   = blockIdx.x * 8 + warp;
    const float* P = g_buf + OFF2;

    if (gw <= K) {
        const float tA = warp_conv(P,          P + NC,     gw,     lane);
        const float tB = warp_conv(P + 2 * NC, P + 3 * NC, K - gw, lane);
        if (lane == 0) g_terms[gw] = tA + tB;
    }
    __syncthreads();
    __threadfence();

    __shared__ unsigned int ticket_s;
    if (threadIdx.x == 0) ticket_s = atomicAdd(&g_done, 1u);
    __syncthreads();
    if (ticket_s != gridDim.x - 1) return;
    __threadfence();

    // Last block: LSE over g_terms[0..K]
    __shared__ float red[8];
    float m = -1e30f;
    for (int i = threadIdx.x; i <= K; i += 256) m = fmaxf(m, __ldcg(&g_terms[i]));
    #pragma unroll
    for (int o = 16; o; o >>= 1) m = fmaxf(m, __shfl_xor_sync(FULL, m, o));
    if (lane == 0) red[warp] = m;
    __syncthreads();
    m = red[lane & 7];
    #pragma unroll
    for (int o = 4; o; o >>= 1) m = fmaxf(m, __shfl_xor_sync(FULL, m, o));
    m = __shfl_sync(FULL, m, 0);              // block max broadcast

    float s = 0.0f;
    for (int i = threadIdx.x; i <= K; i += 256) s += __expf(__ldcg(&g_terms[i]) - m);
    #pragma unroll
    for (int o = 16; o; o >>= 1) s += __shfl_xor_sync(FULL, s, o);
    if (lane == 0) red[warp] = s;
    __syncthreads();
    if (threadIdx.x == 0) {
        float st = 0.0f;
        #pragma unroll
        for (int q = 0; q < 8; ++q) st += red[q];
        out[0] = m + __logf(st);
        g_done = 0;                           // reset for next graph replay
    }
}

// ---------------------------------------------------------------------------
extern "C" void kernel_launch(void* const* d_in, const int* in_sizes, int n_in,
                              void* d_out, int out_size) {
    const float* w   = (const float*)d_in[0];
    const int*   Kp  = (n_in >= 2) ? (const int*)d_in[1] : nullptr;
    float*       out = (float*)d_out;
    (void)in_sizes; (void)out_size;

    // Node 1: leaves (primary; no PDL attribute needed)
    k1_kernel<<<16, 512>>>(w);

    // Secondary nodes: PDL so launch setup overlaps the previous kernel.
    cudaLaunchAttribute attr[1];
    attr[0].id = cudaLaunchAttributeProgrammaticStreamSerialization;
    attr[0].val.programmaticStreamSerializationAllowed = 1;

    cudaLaunchConfig_t cfg = {};
    cfg.blockDim = dim3(256);
    cfg.attrs    = attr;
    cfg.numAttrs = 1;
    cfg.stream   = 0;

    cfg.gridDim = dim3(33, 8);                // 16 -> 8
    { int s = OFF0, d = OFF1; cudaLaunchKernelEx(&cfg, comb_kernel, s, d); }
    cfg.gridDim = dim3(33, 4);                // 8 -> 4
    { int s = OFF1, d = OFF2; cudaLaunchKernelEx(&cfg, comb_kernel, s, d); }
    cfg.gridDim = dim3(33, 1);                // 4 -> scalar
    cudaLaunchKernelEx(&cfg, f4_kernel, Kp, out);
}